// round 10
// baseline (speedup 1.0000x reference)
#include <cuda_runtime.h>

#define HH 256
#define WW 256
#define DIM 512
#define NCELL (HH * WW)
#define V4 (DIM / 4)   // 128 float4 per row
#define NMAX 32768

// Scratch (device globals — no allocation allowed)
__device__ int   g_map[NCELL];    // cell -> point id, -1 if empty
__device__ int   g_min[2] = {0x7fffffff, 0x7fffffff};  // idempotent across replays
__device__ float g_wT[9 * DIM];   // weights reorganized to [tap][channel]
__device__ int   g_bsum[256];     // per-block occupancy counts
__device__ int   g_boff[256];     // exclusive prefix of g_bsum
__device__ int   g_tick;
__device__ volatile int g_done;
__device__ int4  g_tab[NMAX * 3]; // per point: {nbr0..3}{nbr4..7}{nbr8,rank,_,_}

// ---------------------------------------------------------------------------
// Fused prep: clear map, transpose weights, reset scan state, min over pos.
// weight (DIM,1,3,3) -> g_wT[tap*DIM + c], tap = (dh+1)*3 + (dw+1); the
// coefficient for spatial offset (dh,dw) is weight[c][0][dw+1][dh+1]
// (spatial axes transposed because xd = grid.transpose(2,1,0)).
__global__ void k_prep(const int* __restrict__ pos, const float* __restrict__ w,
                       int n) {
    int i = blockIdx.x * blockDim.x + threadIdx.x;
    if (i < NCELL) g_map[i] = -1;
    if (i == 0) { g_tick = 0; g_done = 0; }
    if (i < 9 * DIM) {
        int tap = i / DIM, c = i % DIM;
        int dh = tap / 3 - 1, dw = tap % 3 - 1;
        g_wT[i] = w[c * 9 + (dw + 1) * 3 + (dh + 1)];
    }
    if (i < n) {
        atomicMin(&g_min[0], pos[2 * i]);
        atomicMin(&g_min[1], pos[2 * i + 1]);
    }
}

__global__ void k_scatter(const int* __restrict__ pos, int n) {
    int i = blockIdx.x * blockDim.x + threadIdx.x;
    if (i < n) {
        int p0 = pos[2 * i]     - g_min[0];
        int p1 = pos[2 * i + 1] - g_min[1];
        g_map[p0 * WW + p1] = i;
    }
}

// ---------------------------------------------------------------------------
// Single-pass chip-wide exclusive scan over the occupancy bitmap PLUS
// per-point neighbor-table build (g_map is complete at kernel entry; the 8
// neighbor loads overlap the scan's spin-wait).
__global__ void __launch_bounds__(256) k_scan() {
    const int t = threadIdx.x, b = blockIdx.x;
    const int i = b * 256 + t;
    const int m = g_map[i];
    unsigned bal = __ballot_sync(0xffffffffu, m >= 0);
    const int lane = t & 31, wid = t >> 5;
    const int intra = __popc(bal & ((1u << lane) - 1));

    // Neighbor gather for occupied cells (independent of the scan).
    int nb[9];
    if (m >= 0) {
        const int h = i >> 8, w = i & 255;
#pragma unroll
        for (int tap = 0; tap < 9; ++tap) {
            int hh = h + tap / 3 - 1;
            int ww = w + tap % 3 - 1;
            nb[tap] = (hh >= 0 && hh < HH && ww >= 0 && ww < WW)
                          ? g_map[hh * WW + ww] : -1;
        }
    }

    __shared__ int ws[8], woff[8], s[256];
    __shared__ int slast;
    if (lane == 0) ws[wid] = __popc(bal);
    __syncthreads();
    if (t == 0) {
        int acc = 0;
#pragma unroll
        for (int wv = 0; wv < 8; ++wv) { woff[wv] = acc; acc += ws[wv]; }
        g_bsum[b] = acc;
        __threadfence();
        slast = (atomicAdd(&g_tick, 1) == 255);
    }
    __syncthreads();

    if (slast) {
        __threadfence();                    // acquire published g_bsum
        int mine = g_bsum[t];
        s[t] = mine;
        __syncthreads();
        for (int off = 1; off < 256; off <<= 1) {
            int v = (t >= off) ? s[t - off] : 0;
            __syncthreads();
            s[t] += v;
            __syncthreads();
        }
        g_boff[t] = s[t] - mine;            // exclusive prefix
        __threadfence();
        if (t == 0) g_done = 1;
    } else {
        if (t == 0) { while (g_done == 0) __nanosleep(40); }
        __syncthreads();
        __threadfence();
    }

    if (m >= 0) {
        int rank = g_boff[b] + woff[wid] + intra;
        g_tab[m * 3 + 0] = make_int4(nb[0], nb[1], nb[2], nb[3]);
        g_tab[m * 3 + 1] = make_int4(nb[4], nb[5], nb[6], nb[7]);
        g_tab[m * 3 + 2] = make_int4(nb[8], rank, 0, 0);
    }
}

// ---------------------------------------------------------------------------
// FLAT gather: one thread per (point, 4-channel chunk). No shared memory, no
// sync, no serial loop -> every warp carries ~9 independent L2-latency loads
// and occupancy does the hiding. Absent taps: predicated load (v stays 0),
// exact math (acc += w*0 == acc). Center tap (nbr==self) also provides the
// residual term.
__global__ void __launch_bounds__(256) k_main(
    const float4* __restrict__ x4,
    const float4* __restrict__ bias4,
    float4*       __restrict__ out4,
    int nTot)
{
    const int gid = blockIdx.x * blockDim.x + threadIdx.x;
    const int p = gid >> 7;            // point id
    const int t = gid & 127;           // float4 chunk within row
    if (p >= nTot) return;

    const int4 ta = g_tab[p * 3 + 0];
    const int4 tb = g_tab[p * 3 + 1];
    const int4 tc = g_tab[p * 3 + 2];
    const int nb[9] = {ta.x, ta.y, ta.z, ta.w, tb.x, tb.y, tb.z, tb.w, tc.x};
    const int rank = tc.y;

    const float4* wT4 = (const float4*)g_wT;

    float4 v0 = x4[(size_t)p * V4 + t];      // own row (center tap + residual)
    float4 bre = bias4[t];
    float4 acc;
    acc.x = v0.x + bre.x;
    acc.y = v0.y + bre.y;
    acc.z = v0.z + bre.z;
    acc.w = v0.w + bre.w;

#pragma unroll
    for (int tap = 0; tap < 9; ++tap) {
        float4 v;
        if (tap == 4) {
            v = v0;
        } else {
            int m = nb[tap];
            v = make_float4(0.f, 0.f, 0.f, 0.f);
            if (m >= 0) v = x4[(size_t)m * V4 + t];   // @P LDG.128
        }
        float4 wv = wT4[tap * V4 + t];
        acc.x = fmaf(wv.x, v.x, acc.x);
        acc.y = fmaf(wv.y, v.y, acc.y);
        acc.z = fmaf(wv.z, v.z, acc.z);
        acc.w = fmaf(wv.w, v.w, acc.w);
    }
    out4[(size_t)rank * V4 + t] = acc;
}

// ---------------------------------------------------------------------------
extern "C" void kernel_launch(void* const* d_in, const int* in_sizes, int n_in,
                              void* d_out, int out_size) {
    const float* x    = (const float*)d_in[0];   // (1, N, 512) f32
    const int*   pos  = (const int*)  d_in[1];   // (N, 2) i32
    const float* w    = (const float*)d_in[2];   // (512,1,3,3) f32
    const float* bias = (const float*)d_in[3];   // (512,) f32
    float*       out  = (float*)d_out;           // (1, N, 512) f32

    const int n = in_sizes[1] / 2;

    k_prep   <<<(NCELL + 255) / 256, 256>>>(pos, w, n);
    k_scatter<<<(n + 255) / 256, 256>>>(pos, n);
    k_scan   <<<256, 256>>>();
    k_main   <<<(n * V4 + 255) / 256, 256>>>((const float4*)x,
                                             (const float4*)bias,
                                             (float4*)out, n);
}